// round 6
// baseline (speedup 1.0000x reference)
#include <cuda_runtime.h>
#include <math.h>
#include <stdint.h>

#define HWSZ 16384
#define IMG  128

// -------- scratch (static device memory; no runtime allocation) ------------
#define BUF64 8388608ull   // 8*64*16384 floats
#define BUF32 4194304ull
#define BUF72 9437184ull
static __device__ float g_scratch[4*BUF64 + BUF32 + BUF72];

static __device__ __forceinline__ uint32_t f2tf32(float f){
    uint32_t r; asm("cvt.rna.tf32.f32 %0, %1;" : "=r"(r) : "f"(f)); return r;
}
static __device__ __forceinline__ void mma_tf32(float* c, const uint32_t* a,
                                                uint32_t b0, uint32_t b1){
    asm volatile(
        "mma.sync.aligned.m16n8k8.row.col.f32.tf32.tf32.f32 "
        "{%0,%1,%2,%3}, {%4,%5,%6,%7}, {%8,%9}, {%0,%1,%2,%3};"
        : "+f"(c[0]), "+f"(c[1]), "+f"(c[2]), "+f"(c[3])
        : "r"(a[0]), "r"(a[1]), "r"(a[2]), "r"(a[3]), "r"(b0), "r"(b1));
}

// ---------------------------------------------------------------------------
// tf32 split-precision 1x1-conv GEMM on tensor cores (mma.sync, sm_80+ PTX).
//   D[p, n] = sum_k In[p,k] * W[n,k] (+bias, +optional leaky relu)
//   CTA: 128 pixels x N couts; 8 warps, 16 pixels/warp; K chunked by 32.
//   A,B split fp32 -> tf32 hi+lo; D = Ah*Bh + Al*Bh + Ah*Bl (rel err ~1e-6).
//   gridDim.z selects weight/bias/out segment (fused ops sharing one input).
//   Epilogue staged via smem for coalesced 128-float output runs.
// ---------------------------------------------------------------------------
template<int KC, int N, int SPLIT, int ACT>
__global__ void __launch_bounds__(256)
conv1x1_mma(const float* __restrict__ in0, const float* __restrict__ in1,
            const float* __restrict__ w0, const float* __restrict__ w1,
            const float* __restrict__ w2,
            const float* __restrict__ b0, const float* __restrict__ b1,
            const float* __restrict__ b2,
            float* __restrict__ o0, float* __restrict__ o1, float* __restrict__ o2)
{
    constexpr int NT   = N / 8;       // n-tiles per warp
    constexpr int NPAD = N + 2;
    extern __shared__ __align__(16) char smem[];
    uint32_t* sAhi = (uint32_t*)smem;           // [128][36]
    uint32_t* sAlo = sAhi + 128*36;
    uint32_t* sBhi = sAlo + 128*36;             // [N][36]
    uint32_t* sBlo = sBhi + N*36;

    const int tid  = threadIdx.x;
    const int warp = tid >> 5, lane = tid & 31;
    const int gid  = lane >> 2, tig = lane & 3;
    const int bat  = blockIdx.y;
    const int p0   = blockIdx.x * 128;
    const int seg  = blockIdx.z;

    const float* W  = (seg == 0) ? w0 : (seg == 1) ? w1 : w2;
    const float* Bb = (seg == 0) ? b0 : (seg == 1) ? b1 : b2;
    float*       O  = (seg == 0) ? o0 : (seg == 1) ? o1 : o2;

    float acc[NT][4];
    #pragma unroll
    for (int t = 0; t < NT; t++)
        #pragma unroll
        for (int j = 0; j < 4; j++) acc[t][j] = 0.f;

    for (int c0 = 0; c0 < KC; c0 += 32) {
        __syncthreads();
        // A chunk: 32 k x 128 p, split hi/lo
        for (int idx = tid; idx < 32*128; idx += 256) {
            int k = idx >> 7, p = idx & 127;
            int kg = c0 + k;
            const float* src = (kg < SPLIT)
                ? in0 + ((size_t)bat*SPLIT + kg)*HWSZ
                : in1 + ((size_t)bat*(KC-SPLIT) + (kg-SPLIT))*HWSZ;
            float v = src[p0 + p];
            uint32_t hi = f2tf32(v);
            uint32_t lo = f2tf32(v - __uint_as_float(hi));
            sAhi[p*36 + k] = hi;
            sAlo[p*36 + k] = lo;
        }
        // B chunk: N rows x 32 k
        for (int idx = tid; idx < N*32; idx += 256) {
            int n = idx >> 5, k = idx & 31;
            float v = W[n*KC + c0 + k];
            uint32_t hi = f2tf32(v);
            uint32_t lo = f2tf32(v - __uint_as_float(hi));
            sBhi[n*36 + k] = hi;
            sBlo[n*36 + k] = lo;
        }
        __syncthreads();

        const int pr = warp*16 + gid;
        #pragma unroll
        for (int kk = 0; kk < 32; kk += 8) {
            uint32_t ah[4], al[4];
            ah[0] = sAhi[pr*36     + kk + tig];
            ah[1] = sAhi[(pr+8)*36 + kk + tig];
            ah[2] = sAhi[pr*36     + kk + tig + 4];
            ah[3] = sAhi[(pr+8)*36 + kk + tig + 4];
            al[0] = sAlo[pr*36     + kk + tig];
            al[1] = sAlo[(pr+8)*36 + kk + tig];
            al[2] = sAlo[pr*36     + kk + tig + 4];
            al[3] = sAlo[(pr+8)*36 + kk + tig + 4];
            #pragma unroll
            for (int nt = 0; nt < NT; nt++) {
                int nb = (nt*8 + gid)*36 + kk + tig;
                uint32_t bh0 = sBhi[nb], bh1 = sBhi[nb + 4];
                uint32_t bl0 = sBlo[nb], bl1 = sBlo[nb + 4];
                mma_tf32(acc[nt], ah, bh0, bh1);   // hi*hi
                mma_tf32(acc[nt], al, bh0, bh1);   // lo*hi
                mma_tf32(acc[nt], ah, bl0, bl1);   // hi*lo
            }
        }
    }

    // stage C through smem, then write coalesced
    __syncthreads();
    float* sOut = (float*)smem;   // [128][NPAD]
    {
        const int pr = warp*16 + gid;
        #pragma unroll
        for (int nt = 0; nt < NT; nt++) {
            int nc = nt*8 + tig*2;
            sOut[pr*NPAD + nc]       = acc[nt][0];
            sOut[pr*NPAD + nc + 1]   = acc[nt][1];
            sOut[(pr+8)*NPAD + nc]   = acc[nt][2];
            sOut[(pr+8)*NPAD + nc+1] = acc[nt][3];
        }
    }
    __syncthreads();
    for (int idx = tid; idx < N*128; idx += 256) {
        int n = idx >> 7, p = idx & 127;
        float v = sOut[p*NPAD + n] + (Bb ? Bb[n] : 0.f);
        if (ACT) v = v > 0.f ? v : 0.1f*v;
        O[((size_t)bat*N + n)*HWSZ + p0 + p] = v;
    }
}

static inline constexpr int mma_smem(int N) {
    int ab = (2*128*36 + 2*N*36) * 4;
    int st = 128*(N+2) * 4;
    return ab > st ? ab : st;
}

// ---------------------------------------------------------------------------
// Grouped 3x3 conv (groups=4, 16 in/16 out per group), pad 1, + leaky relu.
// ---------------------------------------------------------------------------
__global__ void __launch_bounds__(256)
convke_kernel(float* __restrict__ out, const float* __restrict__ in,
              const float* __restrict__ w)
{
    const int tid = threadIdx.x;
    const int b = blockIdx.z >> 2, g = blockIdx.z & 3;
    const int x0 = blockIdx.x * 16, y0 = blockIdx.y * 16;
    __shared__ __align__(16) float sv[16][18][18];
    __shared__ __align__(16) float swt[16][9][16];

    for (int i = tid; i < 16*16*9; i += 256) {
        int co = i / 144; int r = i - co*144; int ci = r / 9; int tap = r - ci*9;
        swt[ci][tap][co] = w[((g*16 + co)*16 + ci)*9 + tap];
    }
    for (int i = tid; i < 16*324; i += 256) {
        int ci = i / 324; int r = i - ci*324; int yy = r / 18; int xx = r - yy*18;
        int gy = y0 + yy - 1, gx = x0 + xx - 1;
        float v = 0.f;
        if ((unsigned)gy < 128u && (unsigned)gx < 128u)
            v = in[(((size_t)b*64 + g*16 + ci)*IMG + gy)*IMG + gx];
        sv[ci][yy][xx] = v;
    }
    __syncthreads();

    const int ty = tid >> 4, tx = tid & 15;
    float acc[16];
    #pragma unroll
    for (int c = 0; c < 16; c++) acc[c] = 0.f;

    #pragma unroll
    for (int ci = 0; ci < 16; ci++) {
        float win[9];
        #pragma unroll
        for (int t = 0; t < 9; t++) win[t] = sv[ci][ty + t/3][tx + t%3];
        #pragma unroll
        for (int t = 0; t < 9; t++) {
            #pragma unroll
            for (int q = 0; q < 4; q++) {
                float4 wq = *(const float4*)&swt[ci][t][q*4];
                acc[q*4+0] += win[t]*wq.x;
                acc[q*4+1] += win[t]*wq.y;
                acc[q*4+2] += win[t]*wq.z;
                acc[q*4+3] += win[t]*wq.w;
            }
        }
    }
    #pragma unroll
    for (int co = 0; co < 16; co++) {
        float v = acc[co]; v = v > 0.f ? v : 0.1f*v;
        out[(((size_t)b*64 + g*16 + co)*IMG + y0+ty)*IMG + x0+tx] = v;
    }
}

// ---------------------------------------------------------------------------
// Per-pixel dynamic local conv. Second instance fuses residual add.
// ---------------------------------------------------------------------------
template<bool RESID>
__global__ void __launch_bounds__(256)
localconv_kernel(float* __restrict__ out, const float* __restrict__ v,
                 const float* __restrict__ wd, const float* __restrict__ resid)
{
    const int tid = threadIdx.x;
    const int b = blockIdx.z >> 3, cg = blockIdx.z & 7;
    const int x0 = blockIdx.x * 16, y0 = blockIdx.y * 16;
    __shared__ float sv[8][18][18];

    for (int i = tid; i < 8*324; i += 256) {
        int cl = i / 324; int r = i - cl*324; int yy = r / 18; int xx = r - yy*18;
        int gy = y0 + yy - 1, gx = x0 + xx - 1;
        float val = 0.f;
        if ((unsigned)gy < 128u && (unsigned)gx < 128u)
            val = v[(((size_t)b*64 + cg*8 + cl)*IMG + gy)*IMG + gx];
        sv[cl][yy][xx] = val;
    }
    __syncthreads();

    const int ty = tid >> 4, tx = tid & 15;
    float wt[9];
    #pragma unroll
    for (int t = 0; t < 9; t++)
        wt[t] = wd[(((size_t)b*72 + cg*9 + t)*IMG + y0+ty)*IMG + x0+tx];

    #pragma unroll
    for (int cl = 0; cl < 8; cl++) {
        float a = 0.f;
        #pragma unroll
        for (int t = 0; t < 9; t++) a += sv[cl][ty + t/3][tx + t%3]*wt[t];
        size_t oi = (((size_t)b*64 + cg*8 + cl)*IMG + y0+ty)*IMG + x0+tx;
        out[oi] = RESID ? (a + resid[oi]) : a;
    }
}

// ---------------------------------------------------------------------------
// Softmax over H (axis 2 of [B,72,H,W]) in place.
// ---------------------------------------------------------------------------
__global__ void softmaxH_kernel(float* __restrict__ a)
{
    const int tx = threadIdx.x, ty = threadIdx.y;
    const int w = blockIdx.x*32 + tx;
    const size_t base = (size_t)blockIdx.y * HWSZ + w;   // blockIdx.y = b*72+cc
    float vals[16];
    float mx = -3.4e38f;
    #pragma unroll
    for (int i = 0; i < 16; i++) {
        vals[i] = a[base + (size_t)(ty*16 + i)*IMG];
        mx = fmaxf(mx, vals[i]);
    }
    __shared__ float red[8][32];
    red[ty][tx] = mx;
    __syncthreads();
    float m = red[0][tx];
    #pragma unroll
    for (int j = 1; j < 8; j++) m = fmaxf(m, red[j][tx]);
    __syncthreads();
    float s = 0.f;
    #pragma unroll
    for (int i = 0; i < 16; i++) { vals[i] = __expf(vals[i] - m); s += vals[i]; }
    red[ty][tx] = s;
    __syncthreads();
    float tot = 0.f;
    #pragma unroll
    for (int j = 0; j < 8; j++) tot += red[j][tx];
    float inv = 1.f / tot;
    #pragma unroll
    for (int i = 0; i < 16; i++)
        a[base + (size_t)(ty*16 + i)*IMG] = vals[i]*inv;
}

// ---------------------------------------------------------------------------
extern "C" void kernel_launch(void* const* d_in, const int* in_sizes, int n_in,
                              void* d_out, int out_size)
{
    const float* x      = (const float*)d_in[0];
    const float* phi_w  = (const float*)d_in[1];
    const float* phi_b  = (const float*)d_in[2];
    const float* theta_w= (const float*)d_in[3];
    const float* theta_b= (const float*)d_in[4];
    const float* ke_w   = (const float*)d_in[5];
    const float* e1_w   = (const float*)d_in[6];
    const float* e2_w   = (const float*)d_in[7];
    const float* e2_b   = (const float*)d_in[8];
    const float* c1_w   = (const float*)d_in[9];
    const float* sw1_w  = (const float*)d_in[10];
    const float* sw2_w  = (const float*)d_in[11];
    const float* sw2_b  = (const float*)d_in[12];
    const float* sec_w  = (const float*)d_in[13];
    const float* sec_b  = (const float*)d_in[14];
    float* out = (float*)d_out;

    float* base = nullptr;
    cudaGetSymbolAddress((void**)&base, g_scratch);
    float* q      = base;              // -> lc
    float* v      = base + BUF64;
    float* keypre = base + 2*BUF64;    // -> u
    float* key    = base + 3*BUF64;
    float* t32    = base + 4*BUF64;
    float* w72    = t32 + BUF32;       // -> attn
    float* lc   = q;
    float* u    = keypre;
    float* attn = w72;

    cudaFuncSetAttribute(conv1x1_mma<64,64,64,0>,
        cudaFuncAttributeMaxDynamicSharedMemorySize, mma_smem(64));
    cudaFuncSetAttribute(conv1x1_mma<128,32,64,1>,
        cudaFuncAttributeMaxDynamicSharedMemorySize, mma_smem(32));
    cudaFuncSetAttribute(conv1x1_mma<32,72,32,0>,
        cudaFuncAttributeMaxDynamicSharedMemorySize, mma_smem(72));
    cudaFuncSetAttribute(conv1x1_mma<128,64,64,0>,
        cudaFuncAttributeMaxDynamicSharedMemorySize, mma_smem(64));

    // fused (by grid.z): keypre = phi(x)+b | q = theta(x)+b | v = c1(x)
    conv1x1_mma<64,64,64,0><<<dim3(128,8,3),256,mma_smem(64)>>>(
        x, nullptr, phi_w, theta_w, c1_w, phi_b, theta_b, nullptr,
        keypre, q, v);
    // key = lrelu(grouped 3x3(keypre))
    convke_kernel<<<dim3(8,8,32),256>>>(key, keypre, ke_w);
    // w72 = e2(lrelu(e1([q;key])))
    conv1x1_mma<128,32,64,1><<<dim3(128,8,1),256,mma_smem(32)>>>(
        q, key, e1_w, e1_w, e1_w, nullptr, nullptr, nullptr, t32, t32, t32);
    conv1x1_mma<32,72,32,0><<<dim3(128,8,1),256,mma_smem(72)>>>(
        t32, nullptr, e2_w, e2_w, e2_w, e2_b, e2_b, e2_b, w72, w72, w72);
    // lc = local_conv(v, w72)
    localconv_kernel<false><<<dim3(8,8,64),256>>>(lc, v, w72, nullptr);
    // attn = softmax_H(sw2(lrelu(sw1([lc;key]))))
    conv1x1_mma<128,32,64,1><<<dim3(128,8,1),256,mma_smem(32)>>>(
        lc, key, sw1_w, sw1_w, sw1_w, nullptr, nullptr, nullptr, t32, t32, t32);
    conv1x1_mma<32,72,32,0><<<dim3(128,8,1),256,mma_smem(72)>>>(
        t32, nullptr, sw2_w, sw2_w, sw2_w, sw2_b, sw2_b, sw2_b, attn, attn, attn);
    softmaxH_kernel<<<dim3(4, 8*72), dim3(32,8)>>>(attn);
    // out = local_conv(sec([lc;key]), attn) + x
    conv1x1_mma<128,64,64,0><<<dim3(128,8,1),256,mma_smem(64)>>>(
        lc, key, sec_w, sec_w, sec_w, sec_b, sec_b, sec_b, u, u, u);
    localconv_kernel<true><<<dim3(8,8,64),256>>>(out, u, attn, x);
}

// round 7
// speedup vs baseline: 1.3208x; 1.3208x over previous
#include <cuda_runtime.h>
#include <cuda_bf16.h>
#include <math.h>
#include <stdint.h>

#define HWSZ 16384
#define IMG  128

// -------- scratch (static device memory; no runtime allocation) ------------
// slots: q(->lc), v, keypre(->u), key, w72(->attn). t32 eliminated by fusion.
#define BUF64 8388608ull   // 8*64*16384 floats
#define BUF72 9437184ull
static __device__ float g_scratch[4*BUF64 + BUF72];

// ===================== bf16 split-precision MMA helpers =====================
static __device__ __forceinline__ float lrelu(float v){ return v > 0.f ? v : 0.1f*v; }

// split two fp32 into bf16 hi pair + bf16 lo (residual) pair
static __device__ __forceinline__ void bfsplit2(float v0, float v1,
                                                uint32_t& hi, uint32_t& lo){
    __nv_bfloat16 h0 = __float2bfloat16(v0), h1 = __float2bfloat16(v1);
    float r0 = v0 - __bfloat162float(h0);
    float r1 = v1 - __bfloat162float(h1);
    __nv_bfloat162 H = __halves2bfloat162(h0, h1);
    __nv_bfloat162 L = __halves2bfloat162(__float2bfloat16(r0), __float2bfloat16(r1));
    hi = *(uint32_t*)&H;  lo = *(uint32_t*)&L;
}

static __device__ __forceinline__ void mma_bf16(float* c, const uint32_t* a,
                                                uint32_t b0, uint32_t b1){
    asm volatile(
        "mma.sync.aligned.m16n8k16.row.col.f32.bf16.bf16.f32 "
        "{%0,%1,%2,%3}, {%4,%5,%6,%7}, {%8,%9}, {%0,%1,%2,%3};"
        : "+f"(c[0]), "+f"(c[1]), "+f"(c[2]), "+f"(c[3])
        : "r"(a[0]), "r"(a[1]), "r"(a[2]), "r"(a[3]), "r"(b0), "r"(b1));
}

// smem rows: 32 k-bf16 packed as 16 u32 words, stride 20 words (conflict-free).
// One K=32 chunk of MMAs over NT n-tiles, 3 split terms (hh, lh, hl).
template<int NT>
static __device__ __forceinline__ void mma_chunk(
    const uint32_t* __restrict__ sAh, const uint32_t* __restrict__ sAl,
    const uint32_t* __restrict__ sBh, const uint32_t* __restrict__ sBl,
    int pr, int gid, int tig, float (*acc)[4])
{
    #pragma unroll
    for (int kh = 0; kh < 2; kh++) {
        const int ab = kh*8 + tig;
        uint32_t ah[4], al[4];
        ah[0] = sAh[pr*20 + ab];       ah[1] = sAh[(pr+8)*20 + ab];
        ah[2] = sAh[pr*20 + ab + 4];   ah[3] = sAh[(pr+8)*20 + ab + 4];
        al[0] = sAl[pr*20 + ab];       al[1] = sAl[(pr+8)*20 + ab];
        al[2] = sAl[pr*20 + ab + 4];   al[3] = sAl[(pr+8)*20 + ab + 4];
        #pragma unroll
        for (int nt = 0; nt < NT; nt++) {
            const int nb = (nt*8 + gid)*20 + kh*8 + tig;
            uint32_t bh0 = sBh[nb], bh1 = sBh[nb + 4];
            uint32_t bl0 = sBl[nb], bl1 = sBl[nb + 4];
            mma_bf16(acc[nt], ah, bh0, bh1);
            mma_bf16(acc[nt], al, bh0, bh1);
            mma_bf16(acc[nt], ah, bl0, bl1);
        }
    }
}

// load one K=32 A-chunk (128 pixels) from split input, bf16-split into smem
static __device__ __forceinline__ void load_a_chunk(
    uint32_t* sAh, uint32_t* sAl, const float* __restrict__ in0,
    const float* __restrict__ in1, int split, int c1,
    int c0, int bat, int p0, int tid)
{
    for (int idx = tid; idx < 2048; idx += 256) {
        int k2 = idx >> 7, p = idx & 127;
        int kg = c0 + 2*k2;          // kg even, split even -> pair same tensor
        const float* s = (kg < split)
            ? in0 + ((size_t)bat*split + kg)*HWSZ
            : in1 + ((size_t)bat*c1 + (kg - split))*HWSZ;
        float v0 = s[p0 + p], v1 = s[p0 + p + HWSZ];
        uint32_t hi, lo; bfsplit2(v0, v1, hi, lo);
        sAh[p*20 + k2] = hi;  sAl[p*20 + k2] = lo;
    }
}

// load one K=32 B-chunk (N couts) from row-major W[n][KC]
static __device__ __forceinline__ void load_b_chunk(
    uint32_t* sBh, uint32_t* sBl, const float* __restrict__ W,
    int N, int KC, int c0, int tid)
{
    for (int idx = tid; idx < N*16; idx += 256) {
        int n = idx >> 4, k2 = idx & 15;
        float v0 = W[n*KC + c0 + 2*k2], v1 = W[n*KC + c0 + 2*k2 + 1];
        uint32_t hi, lo; bfsplit2(v0, v1, hi, lo);
        sBh[n*20 + k2] = hi;  sBl[n*20 + k2] = lo;
    }
}

// ---------------------------------------------------------------------------
// Plain 1x1-conv GEMM (bf16 split, tensor cores). CTA: 128 pixels x N couts.
// blockIdx.z selects weight/bias/out segment (fused ops sharing one input).
// ---------------------------------------------------------------------------
template<int KC, int N, int SPLIT, int ACT>
__global__ void __launch_bounds__(256)
conv1x1_bf16(const float* __restrict__ in0, const float* __restrict__ in1,
             const float* __restrict__ w0, const float* __restrict__ w1,
             const float* __restrict__ w2,
             const float* __restrict__ b0, const float* __restrict__ b1,
             const float* __restrict__ b2,
             float* __restrict__ o0, float* __restrict__ o1, float* __restrict__ o2)
{
    constexpr int NT = N/8;
    constexpr int NP = N + 2;
    constexpr int AB = (256 + 2*N)*80;
    constexpr int ST = 128*NP*4;
    constexpr int SMEMB = AB > ST ? AB : ST;
    __shared__ __align__(16) char smem[SMEMB];
    uint32_t* sAh = (uint32_t*)smem;
    uint32_t* sAl = sAh + 128*20;
    uint32_t* sBh = sAl + 128*20;
    uint32_t* sBl = sBh + N*20;
    float* sOut = (float*)smem;

    const int tid = threadIdx.x;
    const int warp = tid >> 5, lane = tid & 31;
    const int gid = lane >> 2, tig = lane & 3;
    const int bat = blockIdx.y, p0 = blockIdx.x*128, seg = blockIdx.z;
    const int pr = warp*16 + gid;

    const float* W  = (seg == 0) ? w0 : (seg == 1) ? w1 : w2;
    const float* Bb = (seg == 0) ? b0 : (seg == 1) ? b1 : b2;
    float*       O  = (seg == 0) ? o0 : (seg == 1) ? o1 : o2;

    float acc[NT][4];
    #pragma unroll
    for (int t = 0; t < NT; t++)
        #pragma unroll
        for (int j = 0; j < 4; j++) acc[t][j] = 0.f;

    for (int c0 = 0; c0 < KC; c0 += 32) {
        __syncthreads();
        load_a_chunk(sAh, sAl, in0, in1, SPLIT, KC-SPLIT, c0, bat, p0, tid);
        load_b_chunk(sBh, sBl, W, N, KC, c0, tid);
        __syncthreads();
        mma_chunk<NT>(sAh, sAl, sBh, sBl, pr, gid, tig, acc);
    }
    __syncthreads();
    #pragma unroll
    for (int nt = 0; nt < NT; nt++) {
        int n = nt*8 + 2*tig;
        sOut[pr*NP + n]     = acc[nt][0];  sOut[pr*NP + n + 1]     = acc[nt][1];
        sOut[(pr+8)*NP + n] = acc[nt][2];  sOut[(pr+8)*NP + n + 1] = acc[nt][3];
    }
    __syncthreads();
    for (int idx = tid; idx < N*128; idx += 256) {
        int n = idx >> 7, p = idx & 127;
        float v = sOut[p*NP + n] + (Bb ? Bb[n] : 0.f);
        if (ACT) v = lrelu(v);
        O[((size_t)bat*N + n)*HWSZ + p0 + p] = v;
    }
}

// ---------------------------------------------------------------------------
// Fused embed chain: O[72] = W2 * lrelu(W1 * [in0;in1]) + b2.
// Stage-1 hidden (32ch) stays in smem (re-split to bf16), never touches DRAM.
// ---------------------------------------------------------------------------
__global__ void __launch_bounds__(256)
embed_fused_kernel(const float* __restrict__ in0, const float* __restrict__ in1,
                   const float* __restrict__ W1, const float* __restrict__ W2,
                   const float* __restrict__ b2, float* __restrict__ O)
{
    __shared__ __align__(16) char smem[37888];
    uint32_t* sAh  = (uint32_t*)smem;
    uint32_t* sAl  = sAh + 128*20;
    uint32_t* sB1h = sAl + 128*20;
    uint32_t* sB1l = sB1h + 32*20;
    uint32_t* sB2h = sAl + 128*20;       // aliases stage-1 B (dead by then)
    uint32_t* sB2l = sB2h + 72*20;
    float* sOut = (float*)smem;

    const int tid = threadIdx.x;
    const int warp = tid >> 5, lane = tid & 31;
    const int gid = lane >> 2, tig = lane & 3;
    const int bat = blockIdx.y, p0 = blockIdx.x*128;
    const int pr = warp*16 + gid;

    float acc1[4][4];
    #pragma unroll
    for (int t = 0; t < 4; t++)
        #pragma unroll
        for (int j = 0; j < 4; j++) acc1[t][j] = 0.f;

    for (int c0 = 0; c0 < 128; c0 += 32) {
        __syncthreads();
        load_a_chunk(sAh, sAl, in0, in1, 64, 64, c0, bat, p0, tid);
        load_b_chunk(sB1h, sB1l, W1, 32, 128, c0, tid);
        __syncthreads();
        mma_chunk<4>(sAh, sAl, sB1h, sB1l, pr, gid, tig, acc1);
    }
    __syncthreads();

    // D1 = lrelu(acc1) -> sA region as bf16 split A-format (K=32 -> words 0..15)
    #pragma unroll
    for (int nt = 0; nt < 4; nt++) {
        uint32_t hi, lo;
        bfsplit2(lrelu(acc1[nt][0]), lrelu(acc1[nt][1]), hi, lo);
        sAh[pr*20 + nt*4 + tig] = hi;  sAl[pr*20 + nt*4 + tig] = lo;
        bfsplit2(lrelu(acc1[nt][2]), lrelu(acc1[nt][3]), hi, lo);
        sAh[(pr+8)*20 + nt*4 + tig] = hi;  sAl[(pr+8)*20 + nt*4 + tig] = lo;
    }
    load_b_chunk(sB2h, sB2l, W2, 72, 32, 0, tid);
    __syncthreads();

    float acc2[9][4];
    #pragma unroll
    for (int t = 0; t < 9; t++)
        #pragma unroll
        for (int j = 0; j < 4; j++) acc2[t][j] = 0.f;
    mma_chunk<9>(sAh, sAl, sB2h, sB2l, pr, gid, tig, acc2);
    __syncthreads();

    #pragma unroll
    for (int nt = 0; nt < 9; nt++) {
        int n = nt*8 + 2*tig;
        sOut[pr*74 + n]     = acc2[nt][0];  sOut[pr*74 + n + 1]     = acc2[nt][1];
        sOut[(pr+8)*74 + n] = acc2[nt][2];  sOut[(pr+8)*74 + n + 1] = acc2[nt][3];
    }
    __syncthreads();
    for (int idx = tid; idx < 72*128; idx += 256) {
        int n = idx >> 7, p = idx & 127;
        float v = sOut[p*74 + n] + b2[n];
        O[((size_t)bat*72 + n)*HWSZ + p0 + p] = v;
    }
}

// ---------------------------------------------------------------------------
// Grouped 3x3 conv (groups=4, 16 in/16 out per group), pad 1, + leaky relu.
// ---------------------------------------------------------------------------
__global__ void __launch_bounds__(256)
convke_kernel(float* __restrict__ out, const float* __restrict__ in,
              const float* __restrict__ w)
{
    const int tid = threadIdx.x;
    const int b = blockIdx.z >> 2, g = blockIdx.z & 3;
    const int x0 = blockIdx.x * 16, y0 = blockIdx.y * 16;
    __shared__ __align__(16) float sv[16][18][18];
    __shared__ __align__(16) float swt[16][9][16];

    for (int i = tid; i < 16*16*9; i += 256) {
        int co = i / 144; int r = i - co*144; int ci = r / 9; int tap = r - ci*9;
        swt[ci][tap][co] = w[((g*16 + co)*16 + ci)*9 + tap];
    }
    for (int i = tid; i < 16*324; i += 256) {
        int ci = i / 324; int r = i - ci*324; int yy = r / 18; int xx = r - yy*18;
        int gy = y0 + yy - 1, gx = x0 + xx - 1;
        float v = 0.f;
        if ((unsigned)gy < 128u && (unsigned)gx < 128u)
            v = in[(((size_t)b*64 + g*16 + ci)*IMG + gy)*IMG + gx];
        sv[ci][yy][xx] = v;
    }
    __syncthreads();

    const int ty = tid >> 4, tx = tid & 15;
    float acc[16];
    #pragma unroll
    for (int c = 0; c < 16; c++) acc[c] = 0.f;

    #pragma unroll
    for (int ci = 0; ci < 16; ci++) {
        float win[9];
        #pragma unroll
        for (int t = 0; t < 9; t++) win[t] = sv[ci][ty + t/3][tx + t%3];
        #pragma unroll
        for (int t = 0; t < 9; t++) {
            #pragma unroll
            for (int q = 0; q < 4; q++) {
                float4 wq = *(const float4*)&swt[ci][t][q*4];
                acc[q*4+0] += win[t]*wq.x;
                acc[q*4+1] += win[t]*wq.y;
                acc[q*4+2] += win[t]*wq.z;
                acc[q*4+3] += win[t]*wq.w;
            }
        }
    }
    #pragma unroll
    for (int co = 0; co < 16; co++) {
        float v = acc[co]; v = v > 0.f ? v : 0.1f*v;
        out[(((size_t)b*64 + g*16 + co)*IMG + y0+ty)*IMG + x0+tx] = v;
    }
}

// ---------------------------------------------------------------------------
// Per-pixel dynamic local conv. Second instance fuses residual add.
// ---------------------------------------------------------------------------
template<bool RESID>
__global__ void __launch_bounds__(256)
localconv_kernel(float* __restrict__ out, const float* __restrict__ v,
                 const float* __restrict__ wd, const float* __restrict__ resid)
{
    const int tid = threadIdx.x;
    const int b = blockIdx.z >> 3, cg = blockIdx.z & 7;
    const int x0 = blockIdx.x * 16, y0 = blockIdx.y * 16;
    __shared__ float sv[8][18][18];

    for (int i = tid; i < 8*324; i += 256) {
        int cl = i / 324; int r = i - cl*324; int yy = r / 18; int xx = r - yy*18;
        int gy = y0 + yy - 1, gx = x0 + xx - 1;
        float val = 0.f;
        if ((unsigned)gy < 128u && (unsigned)gx < 128u)
            val = v[(((size_t)b*64 + cg*8 + cl)*IMG + gy)*IMG + gx];
        sv[cl][yy][xx] = val;
    }
    __syncthreads();

    const int ty = tid >> 4, tx = tid & 15;
    float wt[9];
    #pragma unroll
    for (int t = 0; t < 9; t++)
        wt[t] = wd[(((size_t)b*72 + cg*9 + t)*IMG + y0+ty)*IMG + x0+tx];

    #pragma unroll
    for (int cl = 0; cl < 8; cl++) {
        float a = 0.f;
        #pragma unroll
        for (int t = 0; t < 9; t++) a += sv[cl][ty + t/3][tx + t%3]*wt[t];
        size_t oi = (((size_t)b*64 + cg*8 + cl)*IMG + y0+ty)*IMG + x0+tx;
        out[oi] = RESID ? (a + resid[oi]) : a;
    }
}

// ---------------------------------------------------------------------------
// Softmax over H (axis 2 of [B,72,H,W]) in place.
// ---------------------------------------------------------------------------
__global__ void softmaxH_kernel(float* __restrict__ a)
{
    const int tx = threadIdx.x, ty = threadIdx.y;
    const int w = blockIdx.x*32 + tx;
    const size_t base = (size_t)blockIdx.y * HWSZ + w;   // blockIdx.y = b*72+cc
    float vals[16];
    float mx = -3.4e38f;
    #pragma unroll
    for (int i = 0; i < 16; i++) {
        vals[i] = a[base + (size_t)(ty*16 + i)*IMG];
        mx = fmaxf(mx, vals[i]);
    }
    __shared__ float red[8][32];
    red[ty][tx] = mx;
    __syncthreads();
    float m = red[0][tx];
    #pragma unroll
    for (int j = 1; j < 8; j++) m = fmaxf(m, red[j][tx]);
    __syncthreads();
    float s = 0.f;
    #pragma unroll
    for (int i = 0; i < 16; i++) { vals[i] = __expf(vals[i] - m); s += vals[i]; }
    red[ty][tx] = s;
    __syncthreads();
    float tot = 0.f;
    #pragma unroll
    for (int j = 0; j < 8; j++) tot += red[j][tx];
    float inv = 1.f / tot;
    #pragma unroll
    for (int i = 0; i < 16; i++)
        a[base + (size_t)(ty*16 + i)*IMG] = vals[i]*inv;
}

// ---------------------------------------------------------------------------
extern "C" void kernel_launch(void* const* d_in, const int* in_sizes, int n_in,
                              void* d_out, int out_size)
{
    const float* x      = (const float*)d_in[0];
    const float* phi_w  = (const float*)d_in[1];
    const float* phi_b  = (const float*)d_in[2];
    const float* theta_w= (const float*)d_in[3];
    const float* theta_b= (const float*)d_in[4];
    const float* ke_w   = (const float*)d_in[5];
    const float* e1_w   = (const float*)d_in[6];
    const float* e2_w   = (const float*)d_in[7];
    const float* e2_b   = (const float*)d_in[8];
    const float* c1_w   = (const float*)d_in[9];
    const float* sw1_w  = (const float*)d_in[10];
    const float* sw2_w  = (const float*)d_in[11];
    const float* sw2_b  = (const float*)d_in[12];
    const float* sec_w  = (const float*)d_in[13];
    const float* sec_b  = (const float*)d_in[14];
    float* out = (float*)d_out;

    float* base = nullptr;
    cudaGetSymbolAddress((void**)&base, g_scratch);
    float* q      = base;              // -> lc
    float* v      = base + BUF64;
    float* keypre = base + 2*BUF64;    // -> u
    float* key    = base + 3*BUF64;
    float* w72    = base + 4*BUF64;    // -> attn
    float* lc   = q;
    float* u    = keypre;
    float* attn = w72;

    // fused (by grid.z): keypre = phi(x)+b | q = theta(x)+b | v = c1(x)
    conv1x1_bf16<64,64,64,0><<<dim3(128,8,3),256>>>(
        x, nullptr, phi_w, theta_w, c1_w, phi_b, theta_b, nullptr,
        keypre, q, v);
    // key = lrelu(grouped 3x3(keypre))
    convke_kernel<<<dim3(8,8,32),256>>>(key, keypre, ke_w);
    // w72 = e2(lrelu(e1([q;key])))   -- fused, no hidden in DRAM
    embed_fused_kernel<<<dim3(128,8),256>>>(q, key, e1_w, e2_w, e2_b, w72);
    // lc = local_conv(v, w72)
    localconv_kernel<false><<<dim3(8,8,64),256>>>(lc, v, w72, nullptr);
    // attn = softmax_H(sw2(lrelu(sw1([lc;key]))))  -- fused
    embed_fused_kernel<<<dim3(128,8),256>>>(lc, key, sw1_w, sw2_w, sw2_b, attn);
    softmaxH_kernel<<<dim3(4, 8*72), dim3(32,8)>>>(attn);
    // out = local_conv(sec([lc;key]), attn) + x
    conv1x1_bf16<128,64,64,0><<<dim3(128,8,1),256>>>(
        lc, key, sec_w, sec_w, sec_w, sec_b, sec_b, sec_b, u, u, u);
    localconv_kernel<true><<<dim3(8,8,64),256>>>(out, u, attn, x);
}